// round 10
// baseline (speedup 1.0000x reference)
#include <cuda_runtime.h>
#include <cstdint>

#define B_  16
#define Q_  256
#define K_  256
#define H_  256
#define DV_ 256

__device__ float g_qp[B_ * Q_ * H_];
__device__ float g_kp[B_ * K_ * H_];

__device__ __forceinline__ float tanh_fast(float x) {
    float y;
    asm("tanh.approx.f32 %0, %1;" : "=f"(y) : "f"(x));
    return y;
}

// ---------------------------------------------------------------------------
// Kernel 1: projection GEMM  C[M,256] = A[M,256] * W[256,256]^T  (R1 exact)
// Launched twice; merging measured 2x slower (R2-R4).
// ---------------------------------------------------------------------------
__global__ __launch_bounds__(256) void proj_gemm(const float* __restrict__ A,
                                                 const float* __restrict__ W,
                                                 int sel) {
    constexpr int BM = 64, BN = 64, BK = 32;
    __shared__ float As[BK][BM + 4];
    __shared__ float Bs[BK][BN + 4];

    float* __restrict__ C = sel ? g_kp : g_qp;

    const int tid = threadIdx.x;
    const int m0 = blockIdx.y * BM;
    const int n0 = blockIdx.x * BN;
    const int ty = tid >> 4;
    const int tx = tid & 15;

    float acc[4][4];
#pragma unroll
    for (int i = 0; i < 4; i++)
#pragma unroll
        for (int j = 0; j < 4; j++) acc[i][j] = 0.0f;

    const int lr = tid >> 3;
    const int lc = (tid & 7) * 4;

    for (int kt = 0; kt < H_; kt += BK) {
        float4 a0 = *(const float4*)&A[(m0 + lr) * H_ + kt + lc];
        float4 a1 = *(const float4*)&A[(m0 + lr + 32) * H_ + kt + lc];
        float4 b0 = *(const float4*)&W[(n0 + lr) * H_ + kt + lc];
        float4 b1 = *(const float4*)&W[(n0 + lr + 32) * H_ + kt + lc];

        As[lc + 0][lr] = a0.x; As[lc + 1][lr] = a0.y;
        As[lc + 2][lr] = a0.z; As[lc + 3][lr] = a0.w;
        As[lc + 0][lr + 32] = a1.x; As[lc + 1][lr + 32] = a1.y;
        As[lc + 2][lr + 32] = a1.z; As[lc + 3][lr + 32] = a1.w;
        Bs[lc + 0][lr] = b0.x; Bs[lc + 1][lr] = b0.y;
        Bs[lc + 2][lr] = b0.z; Bs[lc + 3][lr] = b0.w;
        Bs[lc + 0][lr + 32] = b1.x; Bs[lc + 1][lr + 32] = b1.y;
        Bs[lc + 2][lr + 32] = b1.z; Bs[lc + 3][lr + 32] = b1.w;

        __syncthreads();

#pragma unroll
        for (int kk = 0; kk < BK; kk++) {
            float a[4], b[4];
#pragma unroll
            for (int i = 0; i < 4; i++) a[i] = As[kk][ty * 4 + i];
#pragma unroll
            for (int j = 0; j < 4; j++) b[j] = Bs[kk][tx * 4 + j];
#pragma unroll
            for (int i = 0; i < 4; i++)
#pragma unroll
                for (int j = 0; j < 4; j++) acc[i][j] += a[i] * b[j];
        }
        __syncthreads();
    }

#pragma unroll
    for (int i = 0; i < 4; i++) {
        float4 v;
        v.x = acc[i][0]; v.y = acc[i][1]; v.z = acc[i][2]; v.w = acc[i][3];
        *(float4*)&C[(m0 + ty * 4 + i) * H_ + n0 + tx * 4] = v;
    }
}

// ---------------------------------------------------------------------------
// Kernel 2: fused scores + softmax + AV.
// Block = 128 threads, one 4-q-row strip of one batch. Grid = B*Q/4 = 1024.
//   Phase 1 (scores): loop 8 k-tiles (32 rows). k-tile in smem with stride-257
//     rows (conflict-free). Warp = h-chunk (64 h), lane = k, 4 q-rows/thread.
//     Partial sums reduced via pscr.
//   Phase 2: softmax of the 4 rows in smem.
//   Phase 3 (AV): V tiles staged in the same buffer; thread = (q=warp, 8 cols).
// ---------------------------------------------------------------------------
__global__ __launch_bounds__(128) void fused_attn(const float* __restrict__ V,
                                                  const float* __restrict__ wv,
                                                  float* __restrict__ out) {
    __shared__ float ksbuf[32 * 257];            // 32.9 KB k-tile / V-tile
    __shared__ __align__(16) float qs[4][260];   // q strip
    __shared__ __align__(16) float probs[4][260];// scores -> probs
    __shared__ __align__(16) float ws[H_];
    __shared__ float pscr[4][4][33];             // partial sums [hc][q][k]

    const int tid  = threadIdx.x;
    const int b    = blockIdx.x >> 6;
    const int q0   = (blockIdx.x & 63) << 2;
    const int lane = tid & 31;
    const int wid  = tid >> 5;                   // 0..3

    const float* __restrict__ kpb = g_kp + (size_t)b * K_ * H_;
    const float* __restrict__ Vb  = V + (size_t)b * K_ * DV_;

    // ---- load w and q strip ----
    ws[tid] = wv[tid];
    ws[tid + 128] = wv[tid + 128];
#pragma unroll
    for (int i = tid; i < 4 * H_; i += 128) {
        const int r = i >> 8;
        const int c = i & 255;
        qs[r][c] = g_qp[(size_t)(b * Q_ + q0 + r) * H_ + c];
    }

    // ================= Phase 1: scores =================
    const int hbase = wid * 64;
    for (int t = 0; t < 8; t++) {
        const int k0 = t * 32;
        __syncthreads();   // previous tile fully consumed (covers first iter too)
        // fill k-tile: 8192 floats, coalesced LDG, conflict-free STS
#pragma unroll
        for (int i = tid; i < 32 * H_; i += 128) {
            const int r = i >> 8;
            const int c = i & 255;
            ksbuf[r * 257 + c] = kpb[(size_t)(k0 + r) * H_ + c];
        }
        __syncthreads();

        const float* ksrow = &ksbuf[lane * 257];
        float a0 = 0.f, a1 = 0.f, a2 = 0.f, a3 = 0.f;
#pragma unroll 4
        for (int hh = 0; hh < 64; hh += 4) {
            const int h = hbase + hh;
            float4 w4  = *(const float4*)&ws[h];
            float4 q0v = *(const float4*)&qs[0][h];
            float4 q1v = *(const float4*)&qs[1][h];
            float4 q2v = *(const float4*)&qs[2][h];
            float4 q3v = *(const float4*)&qs[3][h];
            float kv0 = ksrow[h + 0];
            float kv1 = ksrow[h + 1];
            float kv2 = ksrow[h + 2];
            float kv3 = ksrow[h + 3];
            a0 = fmaf(w4.x, tanh_fast(q0v.x + kv0), a0);
            a0 = fmaf(w4.y, tanh_fast(q0v.y + kv1), a0);
            a0 = fmaf(w4.z, tanh_fast(q0v.z + kv2), a0);
            a0 = fmaf(w4.w, tanh_fast(q0v.w + kv3), a0);
            a1 = fmaf(w4.x, tanh_fast(q1v.x + kv0), a1);
            a1 = fmaf(w4.y, tanh_fast(q1v.y + kv1), a1);
            a1 = fmaf(w4.z, tanh_fast(q1v.z + kv2), a1);
            a1 = fmaf(w4.w, tanh_fast(q1v.w + kv3), a1);
            a2 = fmaf(w4.x, tanh_fast(q2v.x + kv0), a2);
            a2 = fmaf(w4.y, tanh_fast(q2v.y + kv1), a2);
            a2 = fmaf(w4.z, tanh_fast(q2v.z + kv2), a2);
            a2 = fmaf(w4.w, tanh_fast(q2v.w + kv3), a2);
            a3 = fmaf(w4.x, tanh_fast(q3v.x + kv0), a3);
            a3 = fmaf(w4.y, tanh_fast(q3v.y + kv1), a3);
            a3 = fmaf(w4.z, tanh_fast(q3v.z + kv2), a3);
            a3 = fmaf(w4.w, tanh_fast(q3v.w + kv3), a3);
        }
        pscr[wid][0][lane] = a0;
        pscr[wid][1][lane] = a1;
        pscr[wid][2][lane] = a2;
        pscr[wid][3][lane] = a3;
        __syncthreads();

        // reduce: thread (q=wid, k=lane)
        probs[wid][k0 + lane] = pscr[0][wid][lane] + pscr[1][wid][lane] +
                                pscr[2][wid][lane] + pscr[3][wid][lane];
    }
    __syncthreads();

    // ================= Phase 2: softmax (warp wid -> row wid) =================
    {
        float4 v0 = *(const float4*)&probs[wid][lane * 4];
        float4 v1 = *(const float4*)&probs[wid][128 + lane * 4];
        float mx = fmaxf(fmaxf(fmaxf(v0.x, v0.y), fmaxf(v0.z, v0.w)),
                         fmaxf(fmaxf(v1.x, v1.y), fmaxf(v1.z, v1.w)));
#pragma unroll
        for (int off = 16; off; off >>= 1)
            mx = fmaxf(mx, __shfl_xor_sync(0xffffffffu, mx, off));
        v0.x = __expf(v0.x - mx); v0.y = __expf(v0.y - mx);
        v0.z = __expf(v0.z - mx); v0.w = __expf(v0.w - mx);
        v1.x = __expf(v1.x - mx); v1.y = __expf(v1.y - mx);
        v1.z = __expf(v1.z - mx); v1.w = __expf(v1.w - mx);
        float s = (v0.x + v0.y + v0.z + v0.w) + (v1.x + v1.y + v1.z + v1.w);
#pragma unroll
        for (int off = 16; off; off >>= 1)
            s += __shfl_xor_sync(0xffffffffu, s, off);
        const float inv = 1.0f / s;
        v0.x *= inv; v0.y *= inv; v0.z *= inv; v0.w *= inv;
        v1.x *= inv; v1.y *= inv; v1.z *= inv; v1.w *= inv;
        *(float4*)&probs[wid][lane * 4] = v0;
        *(float4*)&probs[wid][128 + lane * 4] = v1;
    }

    // ================= Phase 3: AV =================
    float acc[8];
#pragma unroll
    for (int j = 0; j < 8; j++) acc[j] = 0.f;

    for (int t = 0; t < 8; t++) {
        const int k0 = t * 32;
        __syncthreads();   // previous V tile consumed (first iter: probs ready)
#pragma unroll
        for (int i = tid; i < 32 * DV_; i += 128) {
            const int r = i >> 8;
            const int c = i & 255;
            ksbuf[r * 257 + c] = Vb[(size_t)(k0 + r) * DV_ + c];
        }
        __syncthreads();

#pragma unroll 4
        for (int k = 0; k < 32; k++) {
            const float a = probs[wid][k0 + k];
            const float* vrow = &ksbuf[k * 257];
#pragma unroll
            for (int j = 0; j < 8; j++)
                acc[j] = fmaf(a, vrow[lane + 32 * j], acc[j]);
        }
    }

    float* orow = &out[(size_t)(b * Q_ + q0 + wid) * DV_];
#pragma unroll
    for (int j = 0; j < 8; j++)
        orow[lane + 32 * j] = acc[j];
}

// ---------------------------------------------------------------------------
extern "C" void kernel_launch(void* const* d_in, const int* in_sizes, int n_in,
                              void* d_out, int out_size) {
    const float* queries = (const float*)d_in[0];
    const float* keys    = (const float*)d_in[1];
    const float* values  = (const float*)d_in[2];
    const float* W_q     = (const float*)d_in[3];
    const float* W_k     = (const float*)d_in[4];
    const float* w_v     = (const float*)d_in[5];
    float* out = (float*)d_out;

    dim3 gproj(H_ / 64, (B_ * Q_) / 64);
    proj_gemm<<<gproj, 256>>>(queries, W_q, 0);
    proj_gemm<<<gproj, 256>>>(keys,    W_k, 1);

    fused_attn<<<(B_ * Q_) / 4, 128>>>(values, w_v, out);
}

// round 11
// speedup vs baseline: 1.0290x; 1.0290x over previous
#include <cuda_runtime.h>
#include <mma.h>
#include <cstdint>

#define B_  16
#define Q_  256
#define K_  256
#define H_  256
#define DV_ 256

__device__ float g_qp[B_ * Q_ * H_];
__device__ float g_kp[B_ * K_ * H_];
__device__ float g_scores[B_ * Q_ * K_];

__device__ __forceinline__ float tanh_fast(float x) {
    float y;
    asm("tanh.approx.f32 %0, %1;" : "=f"(y) : "f"(x));
    return y;
}

// ---------------------------------------------------------------------------
// Kernel 1: projection GEMM via tf32 WMMA.
// C[M,256] = A[M,256] * W[256,256]^T.
// Block = 256 thr (8 warps), tile 64x64; warp tile 16x32 (2 m16n16k8 frags).
// B operand read col-major directly from W (W[n*H + k] == B[k][n]).
// ---------------------------------------------------------------------------
using namespace nvcuda;

__global__ __launch_bounds__(256) void proj_wmma(const float* __restrict__ A,
                                                 const float* __restrict__ W,
                                                 int sel) {
    float* __restrict__ C = sel ? g_kp : g_qp;

    const int warp = threadIdx.x >> 5;
    const int wr = warp >> 1;          // 0..3
    const int wc = warp & 1;           // 0..1
    const int m_base = blockIdx.y * 64 + wr * 16;
    const int n_base = blockIdx.x * 64 + wc * 32;

    wmma::fragment<wmma::accumulator, 16, 16, 8, float> c0, c1;
    wmma::fill_fragment(c0, 0.0f);
    wmma::fill_fragment(c1, 0.0f);

#pragma unroll 4
    for (int k = 0; k < H_; k += 8) {
        wmma::fragment<wmma::matrix_a, 16, 16, 8, wmma::precision::tf32,
                       wmma::row_major> a;
        wmma::load_matrix_sync(a, A + (size_t)m_base * H_ + k, H_);
#pragma unroll
        for (int t = 0; t < a.num_elements; t++)
            a.x[t] = wmma::__float_to_tf32(a.x[t]);

        wmma::fragment<wmma::matrix_b, 16, 16, 8, wmma::precision::tf32,
                       wmma::col_major> b0, b1;
        wmma::load_matrix_sync(b0, W + (size_t)n_base * H_ + k, H_);
        wmma::load_matrix_sync(b1, W + (size_t)(n_base + 16) * H_ + k, H_);
#pragma unroll
        for (int t = 0; t < b0.num_elements; t++) {
            b0.x[t] = wmma::__float_to_tf32(b0.x[t]);
            b1.x[t] = wmma::__float_to_tf32(b1.x[t]);
        }

        wmma::mma_sync(c0, a, b0, c0);
        wmma::mma_sync(c1, a, b1, c1);
    }

    wmma::store_matrix_sync(C + (size_t)m_base * H_ + n_base, c0, H_,
                            wmma::mem_row_major);
    wmma::store_matrix_sync(C + (size_t)m_base * H_ + n_base + 16, c1, H_,
                            wmma::mem_row_major);
}

// ---------------------------------------------------------------------------
// Kernel 2: scores — R1 fp32 MUFU version (at the MUFU floor).
// ---------------------------------------------------------------------------
__global__ __launch_bounds__(256) void scores_kernel(const float* __restrict__ wv) {
    const int b = blockIdx.z;
    const int q0 = blockIdx.y * 32;
    const int k0 = blockIdx.x * 32;

    __shared__ float qs[32][33];
    __shared__ float ks[32][33];
    __shared__ float ws[H_];

    const int tid = threadIdx.x;
    ws[tid] = wv[tid];

    const int ty = tid >> 4;
    const int tx = tid & 15;

    const float* qbase = g_qp + (b * Q_ + q0) * H_;
    const float* kbase = g_kp + (b * K_ + k0) * H_;

    float a00 = 0.f, a01 = 0.f, a10 = 0.f, a11 = 0.f;

    const int lr = tid >> 5;
    const int lc = tid & 31;

    for (int hc = 0; hc < H_; hc += 32) {
        __syncthreads();
#pragma unroll
        for (int rr = 0; rr < 4; rr++) {
            int row = lr + rr * 8;
            qs[row][lc] = qbase[row * H_ + hc + lc];
            ks[row][lc] = kbase[row * H_ + hc + lc];
        }
        __syncthreads();

#pragma unroll
        for (int hh = 0; hh < 32; hh++) {
            float w = ws[hc + hh];
            float qv0 = qs[ty * 2 + 0][hh];
            float qv1 = qs[ty * 2 + 1][hh];
            float kv0 = ks[tx * 2 + 0][hh];
            float kv1 = ks[tx * 2 + 1][hh];
            a00 += w * tanh_fast(qv0 + kv0);
            a01 += w * tanh_fast(qv0 + kv1);
            a10 += w * tanh_fast(qv1 + kv0);
            a11 += w * tanh_fast(qv1 + kv1);
        }
    }

    float* sbase = g_scores + (b * Q_ + q0) * K_ + k0;
    *(float2*)&sbase[(ty * 2 + 0) * K_ + tx * 2] = make_float2(a00, a01);
    *(float2*)&sbase[(ty * 2 + 1) * K_ + tx * 2] = make_float2(a10, a11);
}

// ---------------------------------------------------------------------------
// Kernel 3: in-place row softmax over g_scores. One warp per row.
// ---------------------------------------------------------------------------
__global__ __launch_bounds__(256) void softmax_inplace() {
    const int row = blockIdx.x * 8 + (threadIdx.x >> 5);
    const int lane = threadIdx.x & 31;
    float* srow = g_scores + (size_t)row * K_;

    float4 v0 = *(const float4*)&srow[lane * 4];
    float4 v1 = *(const float4*)&srow[128 + lane * 4];

    float mx = fmaxf(fmaxf(fmaxf(v0.x, v0.y), fmaxf(v0.z, v0.w)),
                     fmaxf(fmaxf(v1.x, v1.y), fmaxf(v1.z, v1.w)));
#pragma unroll
    for (int off = 16; off; off >>= 1)
        mx = fmaxf(mx, __shfl_xor_sync(0xffffffffu, mx, off));

    v0.x = __expf(v0.x - mx); v0.y = __expf(v0.y - mx);
    v0.z = __expf(v0.z - mx); v0.w = __expf(v0.w - mx);
    v1.x = __expf(v1.x - mx); v1.y = __expf(v1.y - mx);
    v1.z = __expf(v1.z - mx); v1.w = __expf(v1.w - mx);

    float s = (v0.x + v0.y + v0.z + v0.w) + (v1.x + v1.y + v1.z + v1.w);
#pragma unroll
    for (int off = 16; off; off >>= 1)
        s += __shfl_xor_sync(0xffffffffu, s, off);
    const float inv = 1.0f / s;

    v0.x *= inv; v0.y *= inv; v0.z *= inv; v0.w *= inv;
    v1.x *= inv; v1.y *= inv; v1.z *= inv; v1.w *= inv;

    *(float4*)&srow[lane * 4] = v0;
    *(float4*)&srow[128 + lane * 4] = v1;
}

// ---------------------------------------------------------------------------
// Kernel 4: AV GEMM (R7 exact).
// ---------------------------------------------------------------------------
__global__ __launch_bounds__(256) void av_gemm(const float* __restrict__ V,
                                               float* __restrict__ out) {
    constexpr int BM = 64, BN = 64, BK = 32;
    __shared__ float As[BK][BM + 4];
    __shared__ float Bs[BK][BN + 4];

    const int tid = threadIdx.x;
    const int m0 = blockIdx.y * BM;
    const int n0 = blockIdx.x * BN;
    const int b = m0 >> 8;
    const float* __restrict__ P = g_scores;
    const float* __restrict__ Vb = V + (size_t)b * K_ * DV_;

    const int ty = tid >> 4;
    const int tx = tid & 15;
    const int lr = tid >> 3;
    const int lc = (tid & 7) * 4;

    float acc[4][4];
#pragma unroll
    for (int i = 0; i < 4; i++)
#pragma unroll
        for (int j = 0; j < 4; j++) acc[i][j] = 0.0f;

    for (int kt = 0; kt < K_; kt += BK) {
        float4 a0 = *(const float4*)&P[(size_t)(m0 + lr) * K_ + kt + lc];
        float4 a1 = *(const float4*)&P[(size_t)(m0 + lr + 32) * K_ + kt + lc];
        float4 b0 = *(const float4*)&Vb[(size_t)(kt + lr) * DV_ + n0 + lc];
        float4 b1 = *(const float4*)&Vb[(size_t)(kt + lr) * DV_ + n0 + 32 + lc];

        As[lc + 0][lr] = a0.x; As[lc + 1][lr] = a0.y;
        As[lc + 2][lr] = a0.z; As[lc + 3][lr] = a0.w;
        As[lc + 0][lr + 32] = a1.x; As[lc + 1][lr + 32] = a1.y;
        As[lc + 2][lr + 32] = a1.z; As[lc + 3][lr + 32] = a1.w;
        *(float4*)&Bs[lr][lc]      = b0;
        *(float4*)&Bs[lr][lc + 32] = b1;

        __syncthreads();

#pragma unroll
        for (int kk = 0; kk < BK; kk++) {
            float a[4], bb[4];
#pragma unroll
            for (int i = 0; i < 4; i++) a[i] = As[kk][ty * 4 + i];
#pragma unroll
            for (int j = 0; j < 4; j++) bb[j] = Bs[kk][tx * 4 + j];
#pragma unroll
            for (int i = 0; i < 4; i++)
#pragma unroll
                for (int j = 0; j < 4; j++) acc[i][j] += a[i] * bb[j];
        }
        __syncthreads();
    }

#pragma unroll
    for (int i = 0; i < 4; i++) {
        float4 v;
        v.x = acc[i][0]; v.y = acc[i][1]; v.z = acc[i][2]; v.w = acc[i][3];
        *(float4*)&out[(size_t)(m0 + ty * 4 + i) * DV_ + n0 + tx * 4] = v;
    }
}

// ---------------------------------------------------------------------------
extern "C" void kernel_launch(void* const* d_in, const int* in_sizes, int n_in,
                              void* d_out, int out_size) {
    const float* queries = (const float*)d_in[0];
    const float* keys    = (const float*)d_in[1];
    const float* values  = (const float*)d_in[2];
    const float* W_q     = (const float*)d_in[3];
    const float* W_k     = (const float*)d_in[4];
    const float* w_v     = (const float*)d_in[5];
    float* out = (float*)d_out;

    dim3 gproj(H_ / 64, (B_ * Q_) / 64);
    proj_wmma<<<gproj, 256>>>(queries, W_q, 0);
    proj_wmma<<<gproj, 256>>>(keys,    W_k, 1);

    dim3 gscores(K_ / 32, Q_ / 32, B_);
    scores_kernel<<<gscores, 256>>>(w_v);

    softmax_inplace<<<(B_ * Q_) / 8, 256>>>();

    dim3 gav(DV_ / 64, (B_ * Q_) / 64);
    av_gemm<<<gav, 256>>>(values, out);
}

// round 12
// speedup vs baseline: 1.1412x; 1.1091x over previous
#include <cuda_runtime.h>
#include <cstdint>

#define B_  16
#define Q_  256
#define K_  256
#define H_  256
#define DV_ 256

__device__ float g_qp[B_ * Q_ * H_];
__device__ float g_kp[B_ * K_ * H_];
__device__ float g_scores[B_ * Q_ * K_];

__device__ __forceinline__ float tanh_fast(float x) {
    float y;
    asm("tanh.approx.f32 %0, %1;" : "=f"(y) : "f"(x));
    return y;
}

// ---------------------------------------------------------------------------
// Kernel 1: projection GEMM  C[M,256] = A[M,256] * W[256,256]^T  (R1 exact)
// Launched twice; merging or WMMA-from-gmem measured slower (R2-R4, R11).
// ---------------------------------------------------------------------------
__global__ __launch_bounds__(256) void proj_gemm(const float* __restrict__ A,
                                                 const float* __restrict__ W,
                                                 int sel) {
    constexpr int BM = 64, BN = 64, BK = 32;
    __shared__ float As[BK][BM + 4];
    __shared__ float Bs[BK][BN + 4];

    float* __restrict__ C = sel ? g_kp : g_qp;

    const int tid = threadIdx.x;
    const int m0 = blockIdx.y * BM;
    const int n0 = blockIdx.x * BN;
    const int ty = tid >> 4;
    const int tx = tid & 15;

    float acc[4][4];
#pragma unroll
    for (int i = 0; i < 4; i++)
#pragma unroll
        for (int j = 0; j < 4; j++) acc[i][j] = 0.0f;

    const int lr = tid >> 3;
    const int lc = (tid & 7) * 4;

    for (int kt = 0; kt < H_; kt += BK) {
        float4 a0 = *(const float4*)&A[(m0 + lr) * H_ + kt + lc];
        float4 a1 = *(const float4*)&A[(m0 + lr + 32) * H_ + kt + lc];
        float4 b0 = *(const float4*)&W[(n0 + lr) * H_ + kt + lc];
        float4 b1 = *(const float4*)&W[(n0 + lr + 32) * H_ + kt + lc];

        As[lc + 0][lr] = a0.x; As[lc + 1][lr] = a0.y;
        As[lc + 2][lr] = a0.z; As[lc + 3][lr] = a0.w;
        As[lc + 0][lr + 32] = a1.x; As[lc + 1][lr + 32] = a1.y;
        As[lc + 2][lr + 32] = a1.z; As[lc + 3][lr + 32] = a1.w;
        Bs[lc + 0][lr] = b0.x; Bs[lc + 1][lr] = b0.y;
        Bs[lc + 2][lr] = b0.z; Bs[lc + 3][lr] = b0.w;
        Bs[lc + 0][lr + 32] = b1.x; Bs[lc + 1][lr + 32] = b1.y;
        Bs[lc + 2][lr + 32] = b1.z; Bs[lc + 3][lr + 32] = b1.w;

        __syncthreads();

#pragma unroll
        for (int kk = 0; kk < BK; kk++) {
            float a[4], b[4];
#pragma unroll
            for (int i = 0; i < 4; i++) a[i] = As[kk][ty * 4 + i];
#pragma unroll
            for (int j = 0; j < 4; j++) b[j] = Bs[kk][tx * 4 + j];
#pragma unroll
            for (int i = 0; i < 4; i++)
#pragma unroll
                for (int j = 0; j < 4; j++) acc[i][j] += a[i] * b[j];
        }
        __syncthreads();
    }

#pragma unroll
    for (int i = 0; i < 4; i++) {
        float4 v;
        v.x = acc[i][0]; v.y = acc[i][1]; v.z = acc[i][2]; v.w = acc[i][3];
        *(float4*)&C[(m0 + ty * 4 + i) * H_ + n0 + tx * 4] = v;
    }
}

// ---------------------------------------------------------------------------
// Kernel 2: fused scores + softmax.
// Block = 4 q-rows x ALL 256 k (thread = k). Grid (Q/4, B) = 1024 blocks —
// same MUFU work/block and granularity as the proven 63us scores kernel.
// K tile (256 x 32 h-chunk) staged in smem, stride-33 rows (conflict-free).
// Softmax done in-block (warps 0-3, one row each); writes normalized probs.
// ---------------------------------------------------------------------------
__global__ __launch_bounds__(256) void scores_softmax(const float* __restrict__ wv) {
    __shared__ float ks[256][33];            // 33.8 KB
    __shared__ float qs[4][H_];
    __shared__ float ws[H_];
    __shared__ __align__(16) float probs[4][260];

    const int tid = threadIdx.x;
    const int b  = blockIdx.y;
    const int q0 = blockIdx.x * 4;

    const float* __restrict__ kpb = g_kp + (size_t)b * K_ * H_;

    ws[tid] = wv[tid];
#pragma unroll
    for (int i = tid; i < 4 * H_; i += 256)
        qs[i >> 8][i & 255] = g_qp[(size_t)(b * Q_ + q0 + (i >> 8)) * H_ + (i & 255)];

    float a0 = 0.f, a1 = 0.f, a2 = 0.f, a3 = 0.f;

    for (int hc = 0; hc < H_; hc += 32) {
        __syncthreads();
#pragma unroll
        for (int i = 0; i < 32; i++) {
            const int idx = i * 256 + tid;
            const int r = idx >> 5;
            const int c = idx & 31;
            ks[r][c] = kpb[(size_t)r * H_ + hc + c];
        }
        __syncthreads();

#pragma unroll 8
        for (int hh = 0; hh < 32; hh++) {
            const float kv = ks[tid][hh];
            const float w  = ws[hc + hh];
            a0 = fmaf(w, tanh_fast(qs[0][hc + hh] + kv), a0);
            a1 = fmaf(w, tanh_fast(qs[1][hc + hh] + kv), a1);
            a2 = fmaf(w, tanh_fast(qs[2][hc + hh] + kv), a2);
            a3 = fmaf(w, tanh_fast(qs[3][hc + hh] + kv), a3);
        }
    }

    probs[0][tid] = a0;
    probs[1][tid] = a1;
    probs[2][tid] = a2;
    probs[3][tid] = a3;
    __syncthreads();

    // warps 0-3: softmax row (warp id) and write normalized probs to gmem
    const int w8 = tid >> 5;
    const int lane = tid & 31;
    if (w8 < 4) {
        float4 v0 = *(const float4*)&probs[w8][lane * 4];
        float4 v1 = *(const float4*)&probs[w8][128 + lane * 4];
        float mx = fmaxf(fmaxf(fmaxf(v0.x, v0.y), fmaxf(v0.z, v0.w)),
                         fmaxf(fmaxf(v1.x, v1.y), fmaxf(v1.z, v1.w)));
#pragma unroll
        for (int off = 16; off; off >>= 1)
            mx = fmaxf(mx, __shfl_xor_sync(0xffffffffu, mx, off));
        v0.x = __expf(v0.x - mx); v0.y = __expf(v0.y - mx);
        v0.z = __expf(v0.z - mx); v0.w = __expf(v0.w - mx);
        v1.x = __expf(v1.x - mx); v1.y = __expf(v1.y - mx);
        v1.z = __expf(v1.z - mx); v1.w = __expf(v1.w - mx);
        float s = (v0.x + v0.y + v0.z + v0.w) + (v1.x + v1.y + v1.z + v1.w);
#pragma unroll
        for (int off = 16; off; off >>= 1)
            s += __shfl_xor_sync(0xffffffffu, s, off);
        const float inv = 1.0f / s;
        v0.x *= inv; v0.y *= inv; v0.z *= inv; v0.w *= inv;
        v1.x *= inv; v1.y *= inv; v1.z *= inv; v1.w *= inv;

        float* srow = g_scores + (size_t)(b * Q_ + q0 + w8) * K_;
        *(float4*)&srow[lane * 4] = v0;
        *(float4*)&srow[128 + lane * 4] = v1;
    }
}

// ---------------------------------------------------------------------------
// Kernel 3: AV GEMM (R7 exact).
// ---------------------------------------------------------------------------
__global__ __launch_bounds__(256) void av_gemm(const float* __restrict__ V,
                                               float* __restrict__ out) {
    constexpr int BM = 64, BN = 64, BK = 32;
    __shared__ float As[BK][BM + 4];
    __shared__ float Bs[BK][BN + 4];

    const int tid = threadIdx.x;
    const int m0 = blockIdx.y * BM;
    const int n0 = blockIdx.x * BN;
    const int b = m0 >> 8;
    const float* __restrict__ P = g_scores;
    const float* __restrict__ Vb = V + (size_t)b * K_ * DV_;

    const int ty = tid >> 4;
    const int tx = tid & 15;
    const int lr = tid >> 3;
    const int lc = (tid & 7) * 4;

    float acc[4][4];
#pragma unroll
    for (int i = 0; i < 4; i++)
#pragma unroll
        for (int j = 0; j < 4; j++) acc[i][j] = 0.0f;

    for (int kt = 0; kt < K_; kt += BK) {
        float4 a0 = *(const float4*)&P[(size_t)(m0 + lr) * K_ + kt + lc];
        float4 a1 = *(const float4*)&P[(size_t)(m0 + lr + 32) * K_ + kt + lc];
        float4 b0 = *(const float4*)&Vb[(size_t)(kt + lr) * DV_ + n0 + lc];
        float4 b1 = *(const float4*)&Vb[(size_t)(kt + lr) * DV_ + n0 + 32 + lc];

        As[lc + 0][lr] = a0.x; As[lc + 1][lr] = a0.y;
        As[lc + 2][lr] = a0.z; As[lc + 3][lr] = a0.w;
        As[lc + 0][lr + 32] = a1.x; As[lc + 1][lr + 32] = a1.y;
        As[lc + 2][lr + 32] = a1.z; As[lc + 3][lr + 32] = a1.w;
        *(float4*)&Bs[lr][lc]      = b0;
        *(float4*)&Bs[lr][lc + 32] = b1;

        __syncthreads();

#pragma unroll
        for (int kk = 0; kk < BK; kk++) {
            float a[4], bb[4];
#pragma unroll
            for (int i = 0; i < 4; i++) a[i] = As[kk][ty * 4 + i];
#pragma unroll
            for (int j = 0; j < 4; j++) bb[j] = Bs[kk][tx * 4 + j];
#pragma unroll
            for (int i = 0; i < 4; i++)
#pragma unroll
                for (int j = 0; j < 4; j++) acc[i][j] += a[i] * bb[j];
        }
        __syncthreads();
    }

#pragma unroll
    for (int i = 0; i < 4; i++) {
        float4 v;
        v.x = acc[i][0]; v.y = acc[i][1]; v.z = acc[i][2]; v.w = acc[i][3];
        *(float4*)&out[(size_t)(m0 + ty * 4 + i) * DV_ + n0 + tx * 4] = v;
    }
}

// ---------------------------------------------------------------------------
extern "C" void kernel_launch(void* const* d_in, const int* in_sizes, int n_in,
                              void* d_out, int out_size) {
    const float* queries = (const float*)d_in[0];
    const float* keys    = (const float*)d_in[1];
    const float* values  = (const float*)d_in[2];
    const float* W_q     = (const float*)d_in[3];
    const float* W_k     = (const float*)d_in[4];
    const float* w_v     = (const float*)d_in[5];
    float* out = (float*)d_out;

    dim3 gproj(H_ / 64, (B_ * Q_) / 64);
    proj_gemm<<<gproj, 256>>>(queries, W_q, 0);
    proj_gemm<<<gproj, 256>>>(keys,    W_k, 1);

    dim3 gss(Q_ / 4, B_);
    scores_softmax<<<gss, 256>>>(w_v);

    dim3 gav(DV_ / 64, (B_ * Q_) / 64);
    av_gemm<<<gav, 256>>>(values, out);
}

// round 13
// speedup vs baseline: 1.2514x; 1.0965x over previous
#include <cuda_runtime.h>
#include <cstdint>

#define B_  16
#define Q_  256
#define K_  256
#define H_  256
#define DV_ 256

__device__ float g_qp[B_ * Q_ * H_];
__device__ float g_kp[B_ * K_ * H_];
__device__ float g_scores[B_ * Q_ * K_];

__device__ __forceinline__ float tanh_fast(float x) {
    float y;
    asm("tanh.approx.f32 %0, %1;" : "=f"(y) : "f"(x));
    return y;
}

// ---------------------------------------------------------------------------
// Kernel 1: projection GEMM, BOTH projections in one launch via blockIdx.z.
// Inner loop is the EXACT R1 body (the only prior z-merge tests also changed
// the inner loop; this isolates the merge).
// ---------------------------------------------------------------------------
__global__ __launch_bounds__(256) void proj_gemm2(const float* __restrict__ Aq,
                                                  const float* __restrict__ Wq,
                                                  const float* __restrict__ Ak,
                                                  const float* __restrict__ Wk) {
    constexpr int BM = 64, BN = 64, BK = 32;
    __shared__ float As[BK][BM + 4];
    __shared__ float Bs[BK][BN + 4];

    const float* __restrict__ A;
    const float* __restrict__ W;
    float* __restrict__ C;
    if (blockIdx.z == 0) { A = Aq; W = Wq; C = g_qp; }
    else                 { A = Ak; W = Wk; C = g_kp; }

    const int tid = threadIdx.x;
    const int m0 = blockIdx.y * BM;
    const int n0 = blockIdx.x * BN;
    const int ty = tid >> 4;
    const int tx = tid & 15;

    float acc[4][4];
#pragma unroll
    for (int i = 0; i < 4; i++)
#pragma unroll
        for (int j = 0; j < 4; j++) acc[i][j] = 0.0f;

    const int lr = tid >> 3;
    const int lc = (tid & 7) * 4;

    for (int kt = 0; kt < H_; kt += BK) {
        float4 a0 = *(const float4*)&A[(m0 + lr) * H_ + kt + lc];
        float4 a1 = *(const float4*)&A[(m0 + lr + 32) * H_ + kt + lc];
        float4 b0 = *(const float4*)&W[(n0 + lr) * H_ + kt + lc];
        float4 b1 = *(const float4*)&W[(n0 + lr + 32) * H_ + kt + lc];

        As[lc + 0][lr] = a0.x; As[lc + 1][lr] = a0.y;
        As[lc + 2][lr] = a0.z; As[lc + 3][lr] = a0.w;
        As[lc + 0][lr + 32] = a1.x; As[lc + 1][lr + 32] = a1.y;
        As[lc + 2][lr + 32] = a1.z; As[lc + 3][lr + 32] = a1.w;
        Bs[lc + 0][lr] = b0.x; Bs[lc + 1][lr] = b0.y;
        Bs[lc + 2][lr] = b0.z; Bs[lc + 3][lr] = b0.w;
        Bs[lc + 0][lr + 32] = b1.x; Bs[lc + 1][lr + 32] = b1.y;
        Bs[lc + 2][lr + 32] = b1.z; Bs[lc + 3][lr + 32] = b1.w;

        __syncthreads();

#pragma unroll
        for (int kk = 0; kk < BK; kk++) {
            float a[4], b[4];
#pragma unroll
            for (int i = 0; i < 4; i++) a[i] = As[kk][ty * 4 + i];
#pragma unroll
            for (int j = 0; j < 4; j++) b[j] = Bs[kk][tx * 4 + j];
#pragma unroll
            for (int i = 0; i < 4; i++)
#pragma unroll
                for (int j = 0; j < 4; j++) acc[i][j] += a[i] * b[j];
        }
        __syncthreads();
    }

#pragma unroll
    for (int i = 0; i < 4; i++) {
        float4 v;
        v.x = acc[i][0]; v.y = acc[i][1]; v.z = acc[i][2]; v.w = acc[i][3];
        *(float4*)&C[(m0 + ty * 4 + i) * H_ + n0 + tx * 4] = v;
    }
}

// ---------------------------------------------------------------------------
// Kernel 2: scores — R1 fp32 MUFU version (at the MUFU floor).
// ---------------------------------------------------------------------------
__global__ __launch_bounds__(256) void scores_kernel(const float* __restrict__ wv) {
    const int b = blockIdx.z;
    const int q0 = blockIdx.y * 32;
    const int k0 = blockIdx.x * 32;

    __shared__ float qs[32][33];
    __shared__ float ks[32][33];
    __shared__ float ws[H_];

    const int tid = threadIdx.x;
    ws[tid] = wv[tid];

    const int ty = tid >> 4;
    const int tx = tid & 15;

    const float* qbase = g_qp + (b * Q_ + q0) * H_;
    const float* kbase = g_kp + (b * K_ + k0) * H_;

    float a00 = 0.f, a01 = 0.f, a10 = 0.f, a11 = 0.f;

    const int lr = tid >> 5;
    const int lc = tid & 31;

    for (int hc = 0; hc < H_; hc += 32) {
        __syncthreads();
#pragma unroll
        for (int rr = 0; rr < 4; rr++) {
            int row = lr + rr * 8;
            qs[row][lc] = qbase[row * H_ + hc + lc];
            ks[row][lc] = kbase[row * H_ + hc + lc];
        }
        __syncthreads();

#pragma unroll
        for (int hh = 0; hh < 32; hh++) {
            float w = ws[hc + hh];
            float qv0 = qs[ty * 2 + 0][hh];
            float qv1 = qs[ty * 2 + 1][hh];
            float kv0 = ks[tx * 2 + 0][hh];
            float kv1 = ks[tx * 2 + 1][hh];
            a00 += w * tanh_fast(qv0 + kv0);
            a01 += w * tanh_fast(qv0 + kv1);
            a10 += w * tanh_fast(qv1 + kv0);
            a11 += w * tanh_fast(qv1 + kv1);
        }
    }

    float* sbase = g_scores + (b * Q_ + q0) * K_ + k0;
    *(float2*)&sbase[(ty * 2 + 0) * K_ + tx * 2] = make_float2(a00, a01);
    *(float2*)&sbase[(ty * 2 + 1) * K_ + tx * 2] = make_float2(a10, a11);
}

// ---------------------------------------------------------------------------
// Kernel 3: in-place row softmax over g_scores. One warp per row.
// ---------------------------------------------------------------------------
__global__ __launch_bounds__(256) void softmax_inplace() {
    const int row = blockIdx.x * 8 + (threadIdx.x >> 5);
    const int lane = threadIdx.x & 31;
    float* srow = g_scores + (size_t)row * K_;

    float4 v0 = *(const float4*)&srow[lane * 4];
    float4 v1 = *(const float4*)&srow[128 + lane * 4];

    float mx = fmaxf(fmaxf(fmaxf(v0.x, v0.y), fmaxf(v0.z, v0.w)),
                     fmaxf(fmaxf(v1.x, v1.y), fmaxf(v1.z, v1.w)));
#pragma unroll
    for (int off = 16; off; off >>= 1)
        mx = fmaxf(mx, __shfl_xor_sync(0xffffffffu, mx, off));

    v0.x = __expf(v0.x - mx); v0.y = __expf(v0.y - mx);
    v0.z = __expf(v0.z - mx); v0.w = __expf(v0.w - mx);
    v1.x = __expf(v1.x - mx); v1.y = __expf(v1.y - mx);
    v1.z = __expf(v1.z - mx); v1.w = __expf(v1.w - mx);

    float s = (v0.x + v0.y + v0.z + v0.w) + (v1.x + v1.y + v1.z + v1.w);
#pragma unroll
    for (int off = 16; off; off >>= 1)
        s += __shfl_xor_sync(0xffffffffu, s, off);
    const float inv = 1.0f / s;

    v0.x *= inv; v0.y *= inv; v0.z *= inv; v0.w *= inv;
    v1.x *= inv; v1.y *= inv; v1.z *= inv; v1.w *= inv;

    *(float4*)&srow[lane * 4] = v0;
    *(float4*)&srow[128 + lane * 4] = v1;
}

// ---------------------------------------------------------------------------
// Kernel 4: AV GEMM (R7 exact).
// ---------------------------------------------------------------------------
__global__ __launch_bounds__(256) void av_gemm(const float* __restrict__ V,
                                               float* __restrict__ out) {
    constexpr int BM = 64, BN = 64, BK = 32;
    __shared__ float As[BK][BM + 4];
    __shared__ float Bs[BK][BN + 4];

    const int tid = threadIdx.x;
    const int m0 = blockIdx.y * BM;
    const int n0 = blockIdx.x * BN;
    const int b = m0 >> 8;
    const float* __restrict__ P = g_scores;
    const float* __restrict__ Vb = V + (size_t)b * K_ * DV_;

    const int ty = tid >> 4;
    const int tx = tid & 15;
    const int lr = tid >> 3;
    const int lc = (tid & 7) * 4;

    float acc[4][4];
#pragma unroll
    for (int i = 0; i < 4; i++)
#pragma unroll
        for (int j = 0; j < 4; j++) acc[i][j] = 0.0f;

    for (int kt = 0; kt < K_; kt += BK) {
        float4 a0 = *(const float4*)&P[(size_t)(m0 + lr) * K_ + kt + lc];
        float4 a1 = *(const float4*)&P[(size_t)(m0 + lr + 32) * K_ + kt + lc];
        float4 b0 = *(const float4*)&Vb[(size_t)(kt + lr) * DV_ + n0 + lc];
        float4 b1 = *(const float4*)&Vb[(size_t)(kt + lr) * DV_ + n0 + 32 + lc];

        As[lc + 0][lr] = a0.x; As[lc + 1][lr] = a0.y;
        As[lc + 2][lr] = a0.z; As[lc + 3][lr] = a0.w;
        As[lc + 0][lr + 32] = a1.x; As[lc + 1][lr + 32] = a1.y;
        As[lc + 2][lr + 32] = a1.z; As[lc + 3][lr + 32] = a1.w;
        *(float4*)&Bs[lr][lc]      = b0;
        *(float4*)&Bs[lr][lc + 32] = b1;

        __syncthreads();

#pragma unroll
        for (int kk = 0; kk < BK; kk++) {
            float a[4], bb[4];
#pragma unroll
            for (int i = 0; i < 4; i++) a[i] = As[kk][ty * 4 + i];
#pragma unroll
            for (int j = 0; j < 4; j++) bb[j] = Bs[kk][tx * 4 + j];
#pragma unroll
            for (int i = 0; i < 4; i++)
#pragma unroll
                for (int j = 0; j < 4; j++) acc[i][j] += a[i] * bb[j];
        }
        __syncthreads();
    }

#pragma unroll
    for (int i = 0; i < 4; i++) {
        float4 v;
        v.x = acc[i][0]; v.y = acc[i][1]; v.z = acc[i][2]; v.w = acc[i][3];
        *(float4*)&out[(size_t)(m0 + ty * 4 + i) * DV_ + n0 + tx * 4] = v;
    }
}

// ---------------------------------------------------------------------------
extern "C" void kernel_launch(void* const* d_in, const int* in_sizes, int n_in,
                              void* d_out, int out_size) {
    const float* queries = (const float*)d_in[0];
    const float* keys    = (const float*)d_in[1];
    const float* values  = (const float*)d_in[2];
    const float* W_q     = (const float*)d_in[3];
    const float* W_k     = (const float*)d_in[4];
    const float* w_v     = (const float*)d_in[5];
    float* out = (float*)d_out;

    dim3 gproj(H_ / 64, (B_ * Q_) / 64, 2);
    proj_gemm2<<<gproj, 256>>>(queries, W_q, keys, W_k);

    dim3 gscores(K_ / 32, Q_ / 32, B_);
    scores_kernel<<<gscores, 256>>>(w_v);

    softmax_inplace<<<(B_ * Q_) / 8, 256>>>();

    dim3 gav(DV_ / 64, (B_ * Q_) / 64);
    av_gemm<<<gav, 256>>>(values, out);
}